// round 2
// baseline (speedup 1.0000x reference)
#include <cuda_runtime.h>
#include <cstdint>

// KatiesDecoder: out[b, v, u*128:(u+1)*128] = z_prime[b, index[v,u], :]
// z_prime (4, 40962, 128) f32; index (163842, 3) int32 (JAX x64-disabled downgrades
// the requested int64 to int32); x_ancil unused. Output: (4, 163842, 384) f32.

static constexpr int B  = 4;
static constexpr int ND = 40962;   // n_dual
static constexpr int D  = 128;     // d_lat
static constexpr int V  = 163842;  // n_vertex
static constexpr int NU = 3;
static constexpr int ROWS_PER_BATCH = V * NU;                          // 491526
static constexpr long long TOTAL_ROWS = (long long)B * ROWS_PER_BATCH; // 1,966,104
static constexpr int VEC_PER_ROW = D / 4;                              // 32 float4

static constexpr int Z_ELEMS   = B * ND * D;  // 20,972,544
static constexpr int IDX_ELEMS = V * NU;      // 491,526

__global__ void __launch_bounds__(256)
katies_gather_kernel(const float4* __restrict__ z,    // (B, ND, 32) float4
                     const int* __restrict__ idx,     // (V, NU) int32
                     float4* __restrict__ out)        // (B, V, 96) float4
{
    long long warp = ((long long)blockIdx.x * blockDim.x + threadIdx.x) >> 5;
    int lane = threadIdx.x & 31;
    if (warp >= TOTAL_ROWS) return;

    int b = (int)(warp / ROWS_PER_BATCH);
    int r = (int)(warp - (long long)b * ROWS_PER_BATCH);
    int v = r / NU;
    int u = r - v * NU;

    int j = __ldg(idx + v * NU + u);   // same addr across warp -> broadcast

    // Source row: z_prime[b, j, :] -> 32 float4, lane i takes the i-th float4.
    const float4* src = z + ((long long)b * ND + j) * VEC_PER_ROW + lane;
    float4 val = __ldg(src);

    // Dest: out[b, v, u*128 + lane*4 ..]; row stride = NU * 32 = 96 float4.
    float4* dst = out + (((long long)b * V + v) * (NU * VEC_PER_ROW))
                      + u * VEC_PER_ROW + lane;
    // Streaming store: keep L2 for the 84 MB z_prime working set (L2 = 126 MB).
    __stcs(dst, val);
}

extern "C" void kernel_launch(void* const* d_in, const int* in_sizes, int n_in,
                              void* d_out, int out_size)
{
    // Bind inputs by element count (robust to ordering surprises).
    const void* z_ptr   = d_in[0];
    const void* idx_ptr = d_in[2];
    for (int i = 0; i < n_in; i++) {
        if (in_sizes[i] == Z_ELEMS)   z_ptr   = d_in[i];
        if (in_sizes[i] == IDX_ELEMS) idx_ptr = d_in[i];
    }

    const float4* z   = (const float4*)z_ptr;
    const int*    idx = (const int*)idx_ptr;
    float4*       out = (float4*)d_out;

    const int threads = 256;   // 8 warps/block -> 8 gathered rows per block
    const long long total_threads = TOTAL_ROWS * 32;
    const int blocks = (int)((total_threads + threads - 1) / threads);

    katies_gather_kernel<<<blocks, threads>>>(z, idx, out);
}

// round 3
// speedup vs baseline: 1.5214x; 1.5214x over previous
#include <cuda_runtime.h>
#include <cstdint>

// KatiesDecoder: out[b, v, u*128:(u+1)*128] = z_prime[b, index[v,u], :]
// z_prime (4, 40962, 128) f32; index (163842, 3) int32; x_ancil unused.
// Output: (4, 163842, 384) f32.
//
// One warp per (b, v): 3 independent gathered LDG.128 (MLP=3) + 3 contiguous
// STG.128 with streaming hint (keep L2 for the 84 MB z_prime working set).

static constexpr int B  = 4;
static constexpr int ND = 40962;   // n_dual
static constexpr int D  = 128;     // d_lat
static constexpr int V  = 163842;  // n_vertex
static constexpr int NU = 3;
static constexpr int VEC = D / 4;  // 32 float4 per latent row

static constexpr int Z_ELEMS   = B * ND * D;  // 20,972,544
static constexpr int IDX_ELEMS = V * NU;      // 491,526

static constexpr int WARPS_PER_BLOCK = 8;
static constexpr int THREADS = WARPS_PER_BLOCK * 32;

__global__ void __launch_bounds__(THREADS)
katies_gather_kernel(const float4* __restrict__ z,   // (B, ND, 32) float4
                     const int* __restrict__ idx,    // (V, NU) int32
                     float4* __restrict__ out)       // (B, V, 96) float4
{
    const int v = blockIdx.x * WARPS_PER_BLOCK + (threadIdx.x >> 5);
    if (v >= V) return;
    const int b = blockIdx.y;
    const int lane = threadIdx.x & 31;

    // 3 broadcast index loads (independent of each other).
    const int* ip = idx + v * NU;
    const int j0 = __ldg(ip + 0);
    const int j1 = __ldg(ip + 1);
    const int j2 = __ldg(ip + 2);

    // 3 independent gathered row reads (mostly L2 hits: 21 MB/batch slice).
    const float4* zb = z + (long long)b * ND * VEC;
    const float4 a0 = __ldg(zb + (long long)j0 * VEC + lane);
    const float4 a1 = __ldg(zb + (long long)j1 * VEC + lane);
    const float4 a2 = __ldg(zb + (long long)j2 * VEC + lane);

    // One contiguous 1536 B destination span per warp.
    float4* dst = out + ((long long)b * V + v) * (NU * VEC) + lane;
    __stcs(dst,           a0);
    __stcs(dst +     VEC, a1);
    __stcs(dst + 2 * VEC, a2);
}

extern "C" void kernel_launch(void* const* d_in, const int* in_sizes, int n_in,
                              void* d_out, int out_size)
{
    // Bind inputs by element count (robust to ordering surprises).
    const void* z_ptr   = d_in[0];
    const void* idx_ptr = d_in[2];
    for (int i = 0; i < n_in; i++) {
        if (in_sizes[i] == Z_ELEMS)   z_ptr   = d_in[i];
        if (in_sizes[i] == IDX_ELEMS) idx_ptr = d_in[i];
    }

    const float4* z   = (const float4*)z_ptr;
    const int*    idx = (const int*)idx_ptr;
    float4*       out = (float4*)d_out;

    dim3 grid((V + WARPS_PER_BLOCK - 1) / WARPS_PER_BLOCK, B);
    katies_gather_kernel<<<grid, THREADS>>>(z, idx, out);
}